// round 12
// baseline (speedup 1.0000x reference)
#include <cuda_runtime.h>
#include <cuda_bf16.h>
#include <cuda_fp16.h>
#include <cstdint>

#define LSEQ   2048
#define BATCH  16
#define NIN    256
#define LANES  8192
#define LANE2  4096
#define ELEMS  (LSEQ * LANES)
#define NCHUNK 64
#define TCHUNK 32

#define NUSED  2560
#define KEFF   256                // single fp16 GEMM
#define NTILE  4                  // M-tiles per CTA
#define NG     16                 // NTILE * 4 k-chunks
#define A_OFF  65536              // after 64KB resident B
#define EPI_OFF 98304             // after B + 2x16KB A stages
#define EPI_H  136                // halves per EPI row (128 + 8 pad, 16B-aligned)
#define GEMM_SMEM (EPI_OFF + 64 * EPI_H * 2)   // 115712

// -------- scratch --------
__device__ __half g_u[5][ELEMS];                // fp16 planes (160MB)
__device__ __half g_xh[32768 * 256];            // A fp16
__device__ __half g_wt[NUSED * KEFF];           // B' fp16 [n-permuted][256]
__device__ float g_A1[NCHUNK * LANES];
__device__ float g_B1[NCHUNK * LANES];
__device__ float g_A2[NCHUNK * LANES];
__device__ float g_B2[NCHUNK * LANES];
__device__ float g_c1in[NCHUNK * LANES];
__device__ float g_c2in[NCHUNK * LANES];

__device__ __forceinline__ float sigmoidf_(float v) {
    return 1.0f / (1.0f + __expf(-v));
}

// ---------------- helpers ----------------
__device__ __forceinline__ uint32_t smem_u32(const void* p) {
    uint32_t a;
    asm("{ .reg .u64 t; cvta.to.shared.u64 t, %1; cvt.u32.u64 %0, t; }" : "=r"(a) : "l"(p));
    return a;
}
__device__ __forceinline__ uint32_t swz(uint32_t b) { return b ^ ((b >> 3) & 0x70); }

__device__ __forceinline__ void cp16(uint32_t dst, const void* src) {
    asm volatile("cp.async.cg.shared.global [%0], [%1], 16;" :: "r"(dst), "l"(src) : "memory");
}
__device__ __forceinline__ void ldsm4(uint32_t* r, uint32_t addr) {
    asm volatile("ldmatrix.sync.aligned.m8n8.x4.shared.b16 {%0,%1,%2,%3}, [%4];"
                 : "=r"(r[0]), "=r"(r[1]), "=r"(r[2]), "=r"(r[3]) : "r"(addr));
}
__device__ __forceinline__ void mma16816h(float* c, const uint32_t* a, const uint32_t* b) {
    asm volatile("mma.sync.aligned.m16n8k16.row.col.f32.f16.f16.f32 "
                 "{%0,%1,%2,%3}, {%4,%5,%6,%7}, {%8,%9}, {%0,%1,%2,%3};"
                 : "+f"(c[0]), "+f"(c[1]), "+f"(c[2]), "+f"(c[3])
                 : "r"(a[0]), "r"(a[1]), "r"(a[2]), "r"(a[3]), "r"(b[0]), "r"(b[1]));
}

// ---------------- prep kernels ----------------
__global__ __launch_bounds__(256)
void cvt_x(const float4* __restrict__ x)
{
    const int idx = blockIdx.x * 256 + threadIdx.x;
    float4 v = x[idx];
    __half2* hp = (__half2*)g_xh;
    hp[idx * 2 + 0] = __floats2half2_rn(v.x, v.y);
    hp[idx * 2 + 1] = __floats2half2_rn(v.z, v.w);
}

__global__ __launch_bounds__(256)
void prep_w(const float* __restrict__ W)   // [256, 3072]
{
    const int idx = blockIdx.x * 256 + threadIdx.x;
    const int p  = idx >> 8;
    const int ko = idx & 255;
    const int dn = p & 511;
    const int kg = p >> 9;
    const int jg = dn * 6 + kg;
    g_wt[idx] = __float2half_rn(W[(size_t)ko * 3072 + jg]);
}

// ---------------- fp16 HMMA GEMM: B-resident, 4 M-tiles per CTA ----------
// Grid (20, 64). CTA: fixed 128-col block, 4x 128-row tiles.
// smem: B 64KB resident | A 2x16KB stream | EPI 17KB fp16 staging.
__global__ __launch_bounds__(256, 2)
void gemm_mma(const float* __restrict__ bias)
{
    extern __shared__ char smem[];
    const uint32_t sb = smem_u32(smem);
    const int tid  = threadIdx.x;
    const int warp = tid >> 5;
    const int lane = tid & 31;
    const int m0 = blockIdx.y * 512;           // 4 tiles of 128 rows
    const int p0 = blockIdx.x * 128;

    const int wm = warp & 3;
    const int wn = warp >> 2;
    const int rb = wm * 32;
    const int cb = wn * 64;

    const int aRow  = rb + (lane & 7) + ((lane >> 3) & 1) * 8;
    const int aCOff = ((lane >> 4) & 1) * 16;
    const int bRow  = cb + (lane & 7) + ((lane >> 4) & 1) * 8;
    const int bCOff = ((lane >> 3) & 1) * 16;

    float acc[2][8][4];
    #pragma unroll
    for (int i = 0; i < 2; i++)
        #pragma unroll
        for (int j = 0; j < 8; j++)
            #pragma unroll
            for (int k = 0; k < 4; k++) acc[i][j][k] = 0.0f;

    const int lr   = tid >> 3;         // 0..31
    const int lc16 = tid & 7;

    // ---- resident B: 4 k-chunks of 128x64 fp16 ----
    #pragma unroll
    for (int kc = 0; kc < 4; kc++)
        #pragma unroll
        for (int j = 0; j < 4; j++) {
            const int row = lr + j * 32;
            cp16(sb + (uint32_t)(kc << 14) + swz((uint32_t)(row * 128 + lc16 * 16)),
                 g_wt + (size_t)(p0 + row) * KEFF + (kc << 6) + lc16 * 8);
        }
    asm volatile("cp.async.commit_group;" ::: "memory");

    #define LOAD_A(g)                                                                   \
    do {                                                                                \
        const int mt_   = m0 + (((g) >> 2) << 7);                                       \
        const int kcl_  = ((g) & 3) << 6;                                               \
        const uint32_t base_ = sb + A_OFF + (uint32_t)(((g) & 1) << 14);                \
        _Pragma("unroll")                                                               \
        for (int j = 0; j < 4; j++) {                                                   \
            const int row_ = lr + j * 32;                                               \
            cp16(base_ + swz((uint32_t)(row_ * 128 + lc16 * 16)),                       \
                 g_xh + (((size_t)(mt_ + row_)) << 8) + kcl_ + lc16 * 8);               \
        }                                                                               \
        asm volatile("cp.async.commit_group;" ::: "memory");                            \
    } while (0)

    LOAD_A(0);

    const int kg  = p0 >> 9;
    const int dnb = p0 & 511;
    __half* plane = g_u[kg];
    __half2* epi = (__half2*)(smem + EPI_OFF);

    for (int g = 0; g < NG; g++) {
        const int kc = g & 3;
        if (g + 1 < NG) {
            LOAD_A(g + 1);
            asm volatile("cp.async.wait_group 1;" ::: "memory");
        } else {
            asm volatile("cp.async.wait_group 0;" ::: "memory");
        }
        __syncthreads();

        const uint32_t aBase = sb + A_OFF + (uint32_t)((g & 1) << 14);
        const uint32_t bBase = sb + (uint32_t)(kc << 14);

        uint32_t afr[2][2][4];
        uint32_t bfr[2][4][4];
        #pragma unroll
        for (int mf = 0; mf < 2; mf++)
            ldsm4(afr[0][mf], aBase + swz((uint32_t)((aRow + mf * 16) * 128 + aCOff)));
        #pragma unroll
        for (int nf = 0; nf < 4; nf++)
            ldsm4(bfr[0][nf], bBase + swz((uint32_t)((bRow + nf * 16) * 128 + bCOff)));

        #pragma unroll
        for (int ks = 0; ks < 4; ks++) {
            const int cur = ks & 1, nxt = cur ^ 1;
            if (ks < 3) {
                const uint32_t co = (uint32_t)((ks + 1) * 32);
                #pragma unroll
                for (int mf = 0; mf < 2; mf++)
                    ldsm4(afr[nxt][mf], aBase + swz((uint32_t)((aRow + mf * 16) * 128) + co + aCOff));
                #pragma unroll
                for (int nf = 0; nf < 4; nf++)
                    ldsm4(bfr[nxt][nf], bBase + swz((uint32_t)((bRow + nf * 16) * 128) + co + bCOff));
            }
            #pragma unroll
            for (int mf = 0; mf < 2; mf++)
                #pragma unroll
                for (int n8 = 0; n8 < 8; n8++)
                    mma16816h(acc[mf][n8], afr[cur][mf], &bfr[cur][n8 >> 1][(n8 & 1) * 2]);
        }
        __syncthreads();

        // -------- per-tile epilogue (overlaps next tile's A prefetch) --------
        if (kc == 3) {
            const int m0t = m0 + ((g >> 2) << 7);
            #pragma unroll 1
            for (int h = 0; h < 2; h++) {
                if ((rb >> 6) == h) {          // wm 0,1 -> half 0 ; wm 2,3 -> half 1
                    const int rloc = (rb & 63) + (lane >> 2);
                    #pragma unroll
                    for (int mf = 0; mf < 2; mf++) {
                        const int r = rloc + mf * 16;
                        #pragma unroll
                        for (int n8 = 0; n8 < 8; n8++) {
                            const int c = cb + (lane & 3) * 2 + n8 * 8;
                            float v0 = acc[mf][n8][0], v1 = acc[mf][n8][1];
                            float v2 = acc[mf][n8][2], v3 = acc[mf][n8][3];
                            if (kg >= 3) {
                                float2 bv = *(const float2*)(bias + kg * 512 + dnb + c);
                                v0 = sigmoidf_(v0 + bv.x); v1 = sigmoidf_(v1 + bv.y);
                                v2 = sigmoidf_(v2 + bv.x); v3 = sigmoidf_(v3 + bv.y);
                            }
                            epi[(r * EPI_H + c) >> 1]       = __floats2half2_rn(v0, v1);
                            epi[((r + 8) * EPI_H + c) >> 1] = __floats2half2_rn(v2, v3);
                        }
                    }
                }
                __syncthreads();
                #pragma unroll
                for (int j = 0; j < 4; j++) {
                    const int idx = tid + j * 256;         // 1024 uint4 = 64 rows x 16
                    const int row = idx >> 4;
                    const int c0  = (idx & 15) * 8;
                    uint4 v = *(uint4*)((__half*)epi + row * EPI_H + c0);
                    *(uint4*)(plane + (size_t)(m0t + h * 64 + row) * 512 + dnb + c0) = v;
                }
                __syncthreads();
            }
            // reset accumulators for next tile
            #pragma unroll
            for (int i = 0; i < 2; i++)
                #pragma unroll
                for (int j = 0; j < 8; j++)
                    #pragma unroll
                    for (int k = 0; k < 4; k++) acc[i][j][k] = 0.0f;
        }
    }
    #undef LOAD_A
}

// ---------------- scan (R8 3-pass, half2 vectorized) ----------------
__device__ __forceinline__ float2 h2f(const __half* p, size_t idx2) {
    __half2 h = *(const __half2*)(p + idx2 * 2);
    return __half22float2(h);
}

__global__ __launch_bounds__(256)
void scan_pass1(const float2* __restrict__ d_init2)
{
    const int gid   = blockIdx.x * blockDim.x + threadIdx.x;
    const int l2    = gid & (LANE2 - 1);
    const int chunk = gid >> 12;
    const int dir   = (l2 >> 7) & 1;
    const int s0    = chunk * TCHUNK;

    float2 d;
    if (s0 == 0) d = d_init2[l2];
    else {
        const int sp = s0 - 1;
        const int tp = dir ? (LSEQ - 1 - sp) : sp;
        d = h2f(g_u[1], (size_t)tp * LANE2 + l2);
    }

    float2 A1 = {1.f, 1.f}, B1 = {0.f, 0.f}, A2 = {1.f, 1.f}, B2 = {0.f, 0.f};
    #pragma unroll 4
    for (int i = 0; i < TCHUNK; i++) {
        const int s = s0 + i;
        const int t = dir ? (LSEQ - 1 - s) : s;
        const size_t b = (size_t)t * LANE2 + l2;
        float2 x1 = h2f(g_u[0], b);
        float2 x2 = h2f(g_u[1], b);
        float2 x3 = h2f(g_u[2], b);
        float2 f1 = h2f(g_u[3], b);
        float2 f2 = h2f(g_u[4], b);
        A1.x *= f1.x; A1.y *= f1.y;
        B1.x = f1.x * B1.x + (1.f - f1.x) * x1.x;
        B1.y = f1.y * B1.y + (1.f - f1.y) * x1.y;
        float tx = x3.x * d.x, ty = x3.y * d.y;
        A2.x *= f2.x; A2.y *= f2.y;
        B2.x = f2.x * B2.x + (1.f - f2.x) * tx;
        B2.y = f2.y * B2.y + (1.f - f2.y) * ty;
        d = x2;
    }
    const int o = chunk * LANE2 + l2;
    ((float2*)g_A1)[o] = A1; ((float2*)g_B1)[o] = B1;
    ((float2*)g_A2)[o] = A2; ((float2*)g_B2)[o] = B2;
}

__global__ __launch_bounds__(256)
void scan_pass2(const float2* __restrict__ c1_init2,
                const float2* __restrict__ c2_init2,
                float* __restrict__ out)
{
    const int l2 = blockIdx.x * blockDim.x + threadIdx.x;
    float2 c1 = c1_init2[l2];
    float2 c2 = c2_init2[l2];
    for (int c = 0; c < NCHUNK; c++) {
        const int o = c * LANE2 + l2;
        ((float2*)g_c1in)[o] = c1;
        ((float2*)g_c2in)[o] = c2;
        float2 A1 = ((const float2*)g_A1)[o], B1 = ((const float2*)g_B1)[o];
        float2 A2 = ((const float2*)g_A2)[o], B2 = ((const float2*)g_B2)[o];
        c1.x = A1.x * c1.x + B1.x;  c1.y = A1.y * c1.y + B1.y;
        c2.x = A2.x * c2.x + B2.x;  c2.y = A2.y * c2.y + B2.y;
    }
    const size_t tail2 = (size_t)LSEQ * LANE2 * 2;
    float2* out2 = (float2*)out;
    out2[tail2 + l2]         = c1;
    out2[tail2 + LANE2 + l2] = c2;
    const int dir = (l2 >> 7) & 1;
    const int tlast = dir ? 0 : (LSEQ - 1);
    out2[tail2 + 2 * LANE2 + l2] = h2f(g_u[1], (size_t)tlast * LANE2 + l2);
}

__global__ __launch_bounds__(256)
void scan_pass3(const float2* __restrict__ d_init2,
                float* __restrict__ out)
{
    const int gid   = blockIdx.x * blockDim.x + threadIdx.x;
    const int l2    = gid & (LANE2 - 1);
    const int chunk = gid >> 12;
    const int dir   = (l2 >> 7) & 1;
    const int s0    = chunk * TCHUNK;

    float2 d;
    if (s0 == 0) d = d_init2[l2];
    else {
        const int sp = s0 - 1;
        const int tp = dir ? (LSEQ - 1 - sp) : sp;
        d = h2f(g_u[1], (size_t)tp * LANE2 + l2);
    }

    const int o = chunk * LANE2 + l2;
    float2 c1 = ((const float2*)g_c1in)[o];
    float2 c2 = ((const float2*)g_c2in)[o];
    float2* out_c1 = (float2*)out;
    float2* out_c2 = out_c1 + (size_t)LSEQ * LANE2;

    #pragma unroll 4
    for (int i = 0; i < TCHUNK; i++) {
        const int s = s0 + i;
        const int t = dir ? (LSEQ - 1 - s) : s;
        const size_t b = (size_t)t * LANE2 + l2;
        float2 x1 = h2f(g_u[0], b);
        float2 x2 = h2f(g_u[1], b);
        float2 x3 = h2f(g_u[2], b);
        float2 f1 = h2f(g_u[3], b);
        float2 f2 = h2f(g_u[4], b);
        c1.x = (c1.x - x1.x) * f1.x + x1.x;
        c1.y = (c1.y - x1.y) * f1.y + x1.y;
        float tx = x3.x * d.x, ty = x3.y * d.y;
        c2.x = (c2.x - tx) * f2.x + tx;
        c2.y = (c2.y - ty) * f2.y + ty;
        d = x2;
        out_c1[b] = c1;
        out_c2[b] = c2;
    }
}

// ======================================================================
extern "C" void kernel_launch(void* const* d_in, const int* in_sizes, int n_in,
                              void* d_out, int out_size)
{
    const float* x    = (const float*)d_in[0];
    const float* w    = (const float*)d_in[1];
    const float* bias = (const float*)d_in[2];
    const float* c1i  = (const float*)d_in[3];
    const float* c2i  = (const float*)d_in[4];
    const float* di   = (const float*)d_in[5];
    float* out = (float*)d_out;

    static int attr_set = 0;
    if (!attr_set) {
        cudaFuncSetAttribute(gemm_mma, cudaFuncAttributeMaxDynamicSharedMemorySize, GEMM_SMEM);
        attr_set = 1;
    }

    cvt_x<<<8192, 256>>>((const float4*)x);
    prep_w<<<2560, 256>>>(w);
    gemm_mma<<<dim3(20, 64), 256, GEMM_SMEM>>>(bias);

    scan_pass1<<<(NCHUNK * LANE2) / 256, 256>>>((const float2*)di);
    scan_pass2<<<LANE2 / 256, 256>>>((const float2*)c1i, (const float2*)c2i, out);
    scan_pass3<<<(NCHUNK * LANE2) / 256, 256>>>((const float2*)di, out);
}

// round 14
// speedup vs baseline: 1.5281x; 1.5281x over previous
#include <cuda_runtime.h>
#include <cuda_bf16.h>
#include <cuda_fp16.h>
#include <cstdint>

#define LSEQ   2048
#define BATCH  16
#define NIN    256
#define LANES  8192
#define LANE2  4096
#define ELEMS  (LSEQ * LANES)
#define NCHUNK 64
#define TCHUNK 32

#define NUSED  2560
#define KEFF   256               // single fp16 GEMM
#define NKCH   4
#define NSTAGE 3
#define STAGE_BYTES 32768
#define EPI_STRIDE 132
#define GEMM_SMEM  (NSTAGE * STAGE_BYTES)

// -------- scratch --------
__device__ __half g_u[5][ELEMS];                // fp16 planes (160MB)
__device__ __half g_xh[32768 * 256];            // A fp16
__device__ __half g_wt[NUSED * KEFF];           // B' fp16 [n-permuted][256]
__device__ float g_A1[NCHUNK * LANES];
__device__ float g_B1[NCHUNK * LANES];
__device__ float g_A2[NCHUNK * LANES];
__device__ float g_B2[NCHUNK * LANES];
__device__ float g_c1in[NCHUNK * LANES];
__device__ float g_c2in[NCHUNK * LANES];

__device__ __forceinline__ float sigmoidf_(float v) {
    return 1.0f / (1.0f + __expf(-v));
}

// ---------------- helpers ----------------
__device__ __forceinline__ uint32_t smem_u32(const void* p) {
    uint32_t a;
    asm("{ .reg .u64 t; cvta.to.shared.u64 t, %1; cvt.u32.u64 %0, t; }" : "=r"(a) : "l"(p));
    return a;
}
__device__ __forceinline__ uint32_t swz(uint32_t b) { return b ^ ((b >> 3) & 0x70); }

__device__ __forceinline__ void cp16(uint32_t dst, const void* src) {
    asm volatile("cp.async.cg.shared.global [%0], [%1], 16;" :: "r"(dst), "l"(src) : "memory");
}
__device__ __forceinline__ void ldsm4(uint32_t* r, uint32_t addr) {
    asm volatile("ldmatrix.sync.aligned.m8n8.x4.shared.b16 {%0,%1,%2,%3}, [%4];"
                 : "=r"(r[0]), "=r"(r[1]), "=r"(r[2]), "=r"(r[3]) : "r"(addr));
}
__device__ __forceinline__ void mma16816h(float* c, const uint32_t* a, const uint32_t* b) {
    asm volatile("mma.sync.aligned.m16n8k16.row.col.f32.f16.f16.f32 "
                 "{%0,%1,%2,%3}, {%4,%5,%6,%7}, {%8,%9}, {%0,%1,%2,%3};"
                 : "+f"(c[0]), "+f"(c[1]), "+f"(c[2]), "+f"(c[3])
                 : "r"(a[0]), "r"(a[1]), "r"(a[2]), "r"(a[3]), "r"(b[0]), "r"(b[1]));
}

// ---------------- merged prep kernel ----------------
// blocks [0, 8192): convert x (2M float4)
// blocks [8192, 10752): permute+convert W (655360 elems)
__global__ __launch_bounds__(256)
void prep_all(const float4* __restrict__ x, const float* __restrict__ W)
{
    const int b = blockIdx.x;
    if (b < 8192) {
        const int idx = b * 256 + threadIdx.x;
        float4 v = x[idx];
        __half2* hp = (__half2*)g_xh;
        hp[idx * 2 + 0] = __floats2half2_rn(v.x, v.y);
        hp[idx * 2 + 1] = __floats2half2_rn(v.z, v.w);
    } else {
        const int idx = (b - 8192) * 256 + threadIdx.x;
        const int p  = idx >> 8;
        const int ko = idx & 255;
        const int dn = p & 511;
        const int kg = p >> 9;
        const int jg = dn * 6 + kg;
        g_wt[idx] = __float2half_rn(W[(size_t)ko * 3072 + jg]);
    }
}

// ---------------- fp16 HMMA GEMM (R8-exact pipeline ordering) ----------
// C[32768, 2560] = A[32768,256] @ B'^T.  Grid (20, 256); CTA 128x128;
// 8 warps (4m x 2n), warp tile 32x64; K chunks of 64, NSTAGE=3.
__global__ __launch_bounds__(256)
void gemm_mma(const float* __restrict__ bias)
{
    extern __shared__ char smem[];
    const uint32_t sb = smem_u32(smem);
    const int tid  = threadIdx.x;
    const int warp = tid >> 5;
    const int lane = tid & 31;
    const int m0 = blockIdx.y * 128;
    const int p0 = blockIdx.x * 128;

    const int wm = warp & 3;
    const int wn = warp >> 2;
    const int rb = wm * 32;
    const int cb = wn * 64;

    const int aRow  = rb + (lane & 7) + ((lane >> 3) & 1) * 8;
    const int aCOff = ((lane >> 4) & 1) * 16;
    const int bRow  = cb + (lane & 7) + ((lane >> 4) & 1) * 8;
    const int bCOff = ((lane >> 3) & 1) * 16;

    float acc[2][8][4];
    #pragma unroll
    for (int i = 0; i < 2; i++)
        #pragma unroll
        for (int j = 0; j < 8; j++)
            #pragma unroll
            for (int k = 0; k < 4; k++) acc[i][j][k] = 0.0f;

    const int lr   = tid >> 3;
    const int lc16 = tid & 7;

    #define LOAD_STAGE(i, s)                                                            \
    do {                                                                                \
        const int kc_ = (i) << 6;                                                       \
        const uint32_t base_ = sb + (uint32_t)(s) * STAGE_BYTES;                        \
        _Pragma("unroll")                                                               \
        for (int j = 0; j < 4; j++) {                                                   \
            const int row_ = lr + j * 32;                                               \
            cp16(base_ + swz((uint32_t)(row_ * 128 + lc16 * 16)),                       \
                 g_xh + (((size_t)(m0 + row_)) << 8) + kc_ + lc16 * 8);                 \
        }                                                                               \
        _Pragma("unroll")                                                               \
        for (int j = 0; j < 4; j++) {                                                   \
            const int row_ = lr + j * 32;                                               \
            cp16(base_ + 16384u + swz((uint32_t)(row_ * 128 + lc16 * 16)),              \
                 g_wt + (size_t)(p0 + row_) * KEFF + kc_ + lc16 * 8);                   \
        }                                                                               \
        asm volatile("cp.async.commit_group;" ::: "memory");                            \
    } while (0)

    LOAD_STAGE(0, 0);
    LOAD_STAGE(1, 1);

    int stage = 0;
    for (int i = 0; i < NKCH; i++) {
        asm volatile("cp.async.wait_group 1;" ::: "memory");
        __syncthreads();

        if (i + 2 < NKCH) {
            const int s2 = (stage + 2 >= NSTAGE) ? (stage + 2 - NSTAGE) : (stage + 2);
            LOAD_STAGE(i + 2, s2);
        }

        const uint32_t aBase = sb + (uint32_t)stage * STAGE_BYTES;
        const uint32_t bBase = aBase + 16384u;

        uint32_t afr[2][2][4];
        uint32_t bfr[2][4][4];
        #pragma unroll
        for (int mf = 0; mf < 2; mf++)
            ldsm4(afr[0][mf], aBase + swz((uint32_t)((aRow + mf * 16) * 128 + aCOff)));
        #pragma unroll
        for (int nf = 0; nf < 4; nf++)
            ldsm4(bfr[0][nf], bBase + swz((uint32_t)((bRow + nf * 16) * 128 + bCOff)));

        #pragma unroll
        for (int ks = 0; ks < 4; ks++) {
            const int cur = ks & 1, nxt = cur ^ 1;
            if (ks < 3) {
                const uint32_t co = (uint32_t)((ks + 1) * 32);
                #pragma unroll
                for (int mf = 0; mf < 2; mf++)
                    ldsm4(afr[nxt][mf], aBase + swz((uint32_t)((aRow + mf * 16) * 128) + co + aCOff));
                #pragma unroll
                for (int nf = 0; nf < 4; nf++)
                    ldsm4(bfr[nxt][nf], bBase + swz((uint32_t)((bRow + nf * 16) * 128) + co + bCOff));
            }
            #pragma unroll
            for (int mf = 0; mf < 2; mf++)
                #pragma unroll
                for (int n8 = 0; n8 < 8; n8++)
                    mma16816h(acc[mf][n8], afr[cur][mf], &bfr[cur][n8 >> 1][(n8 & 1) * 2]);
        }

        stage = (stage + 1 >= NSTAGE) ? 0 : stage + 1;
    }
    #undef LOAD_STAGE

    __syncthreads();

    // -------- epilogue: acc -> smem (fp32) -> fp16 g_u plane --------
    float* smf = (float*)smem;
    {
        const int r0 = rb + (lane >> 2);
        const int c0 = cb + (lane & 3) * 2;
        #pragma unroll
        for (int mf = 0; mf < 2; mf++) {
            const int r = r0 + mf * 16;
            #pragma unroll
            for (int n8 = 0; n8 < 8; n8++) {
                const int c = c0 + n8 * 8;
                *(float2*)&smf[r * EPI_STRIDE + c]       = make_float2(acc[mf][n8][0], acc[mf][n8][1]);
                *(float2*)&smf[(r + 8) * EPI_STRIDE + c] = make_float2(acc[mf][n8][2], acc[mf][n8][3]);
            }
        }
    }
    __syncthreads();

    const int kg  = p0 >> 9;
    const int dnb = p0 & 511;
    __half* plane = g_u[kg];
    const int cc = lane * 4;
    if (kg >= 3) {
        const float* bp = bias + kg * 512 + dnb;
        float4 bv = *(const float4*)(bp + cc);
        #pragma unroll
        for (int t = 0; t < 16; t++) {
            const int r = warp * 16 + t;
            float4 v = *(float4*)&smf[r * EPI_STRIDE + cc];
            __half2 p0h = __floats2half2_rn(sigmoidf_(v.x + bv.x), sigmoidf_(v.y + bv.y));
            __half2 p1h = __floats2half2_rn(sigmoidf_(v.z + bv.z), sigmoidf_(v.w + bv.w));
            uint2 u2;
            u2.x = *(unsigned*)&p0h;
            u2.y = *(unsigned*)&p1h;
            *(uint2*)(plane + (size_t)(m0 + r) * 512 + dnb + cc) = u2;
        }
    } else {
        #pragma unroll
        for (int t = 0; t < 16; t++) {
            const int r = warp * 16 + t;
            float4 v = *(float4*)&smf[r * EPI_STRIDE + cc];
            __half2 p0h = __floats2half2_rn(v.x, v.y);
            __half2 p1h = __floats2half2_rn(v.z, v.w);
            uint2 u2;
            u2.x = *(unsigned*)&p0h;
            u2.y = *(unsigned*)&p1h;
            *(uint2*)(plane + (size_t)(m0 + r) * 512 + dnb + cc) = u2;
        }
    }
}

// ---------------- scan (R8 3-pass, half2 vectorized) ----------------
__device__ __forceinline__ float2 h2f(const __half* p, size_t idx2) {
    __half2 h = *(const __half2*)(p + idx2 * 2);
    return __half22float2(h);
}

__global__ __launch_bounds__(256)
void scan_pass1(const float2* __restrict__ d_init2)
{
    const int gid   = blockIdx.x * blockDim.x + threadIdx.x;
    const int l2    = gid & (LANE2 - 1);
    const int chunk = gid >> 12;
    const int dir   = (l2 >> 7) & 1;
    const int s0    = chunk * TCHUNK;

    float2 d;
    if (s0 == 0) d = d_init2[l2];
    else {
        const int sp = s0 - 1;
        const int tp = dir ? (LSEQ - 1 - sp) : sp;
        d = h2f(g_u[1], (size_t)tp * LANE2 + l2);
    }

    float2 A1 = {1.f, 1.f}, B1 = {0.f, 0.f}, A2 = {1.f, 1.f}, B2 = {0.f, 0.f};
    #pragma unroll 4
    for (int i = 0; i < TCHUNK; i++) {
        const int s = s0 + i;
        const int t = dir ? (LSEQ - 1 - s) : s;
        const size_t b = (size_t)t * LANE2 + l2;
        float2 x1 = h2f(g_u[0], b);
        float2 x2 = h2f(g_u[1], b);
        float2 x3 = h2f(g_u[2], b);
        float2 f1 = h2f(g_u[3], b);
        float2 f2 = h2f(g_u[4], b);
        A1.x *= f1.x; A1.y *= f1.y;
        B1.x = f1.x * B1.x + (1.f - f1.x) * x1.x;
        B1.y = f1.y * B1.y + (1.f - f1.y) * x1.y;
        float tx = x3.x * d.x, ty = x3.y * d.y;
        A2.x *= f2.x; A2.y *= f2.y;
        B2.x = f2.x * B2.x + (1.f - f2.x) * tx;
        B2.y = f2.y * B2.y + (1.f - f2.y) * ty;
        d = x2;
    }
    const int o = chunk * LANE2 + l2;
    ((float2*)g_A1)[o] = A1; ((float2*)g_B1)[o] = B1;
    ((float2*)g_A2)[o] = A2; ((float2*)g_B2)[o] = B2;
}

__global__ __launch_bounds__(256)
void scan_pass2(const float2* __restrict__ c1_init2,
                const float2* __restrict__ c2_init2,
                float* __restrict__ out)
{
    const int l2 = blockIdx.x * blockDim.x + threadIdx.x;
    float2 c1 = c1_init2[l2];
    float2 c2 = c2_init2[l2];
    #pragma unroll 8
    for (int c = 0; c < NCHUNK; c++) {
        const int o = c * LANE2 + l2;
        ((float2*)g_c1in)[o] = c1;
        ((float2*)g_c2in)[o] = c2;
        float2 A1 = ((const float2*)g_A1)[o], B1 = ((const float2*)g_B1)[o];
        float2 A2 = ((const float2*)g_A2)[o], B2 = ((const float2*)g_B2)[o];
        c1.x = A1.x * c1.x + B1.x;  c1.y = A1.y * c1.y + B1.y;
        c2.x = A2.x * c2.x + B2.x;  c2.y = A2.y * c2.y + B2.y;
    }
    const size_t tail2 = (size_t)LSEQ * LANE2 * 2;
    float2* out2 = (float2*)out;
    out2[tail2 + l2]         = c1;
    out2[tail2 + LANE2 + l2] = c2;
    const int dir = (l2 >> 7) & 1;
    const int tlast = dir ? 0 : (LSEQ - 1);
    out2[tail2 + 2 * LANE2 + l2] = h2f(g_u[1], (size_t)tlast * LANE2 + l2);
}

__global__ __launch_bounds__(256)
void scan_pass3(const float2* __restrict__ d_init2,
                float* __restrict__ out)
{
    const int gid   = blockIdx.x * blockDim.x + threadIdx.x;
    const int l2    = gid & (LANE2 - 1);
    const int chunk = gid >> 12;
    const int dir   = (l2 >> 7) & 1;
    const int s0    = chunk * TCHUNK;

    float2 d;
    if (s0 == 0) d = d_init2[l2];
    else {
        const int sp = s0 - 1;
        const int tp = dir ? (LSEQ - 1 - sp) : sp;
        d = h2f(g_u[1], (size_t)tp * LANE2 + l2);
    }

    const int o = chunk * LANE2 + l2;
    float2 c1 = ((const float2*)g_c1in)[o];
    float2 c2 = ((const float2*)g_c2in)[o];
    float2* out_c1 = (float2*)out;
    float2* out_c2 = out_c1 + (size_t)LSEQ * LANE2;

    #pragma unroll 4
    for (int i = 0; i < TCHUNK; i++) {
        const int s = s0 + i;
        const int t = dir ? (LSEQ - 1 - s) : s;
        const size_t b = (size_t)t * LANE2 + l2;
        float2 x1 = h2f(g_u[0], b);
        float2 x2 = h2f(g_u[1], b);
        float2 x3 = h2f(g_u[2], b);
        float2 f1 = h2f(g_u[3], b);
        float2 f2 = h2f(g_u[4], b);
        c1.x = (c1.x - x1.x) * f1.x + x1.x;
        c1.y = (c1.y - x1.y) * f1.y + x1.y;
        float tx = x3.x * d.x, ty = x3.y * d.y;
        c2.x = (c2.x - tx) * f2.x + tx;
        c2.y = (c2.y - ty) * f2.y + ty;
        d = x2;
        out_c1[b] = c1;
        out_c2[b] = c2;
    }
}

// ======================================================================
extern "C" void kernel_launch(void* const* d_in, const int* in_sizes, int n_in,
                              void* d_out, int out_size)
{
    const float* x    = (const float*)d_in[0];
    const float* w    = (const float*)d_in[1];
    const float* bias = (const float*)d_in[2];
    const float* c1i  = (const float*)d_in[3];
    const float* c2i  = (const float*)d_in[4];
    const float* di   = (const float*)d_in[5];
    float* out = (float*)d_out;

    static int attr_set = 0;
    if (!attr_set) {
        cudaFuncSetAttribute(gemm_mma, cudaFuncAttributeMaxDynamicSharedMemorySize, GEMM_SMEM);
        attr_set = 1;
    }

    prep_all<<<8192 + 2560, 256>>>((const float4*)x, w);
    gemm_mma<<<dim3(20, 256), 256, GEMM_SMEM>>>(bias);

    scan_pass1<<<(NCHUNK * LANE2) / 256, 256>>>((const float2*)di);
    scan_pass2<<<LANE2 / 256, 256>>>((const float2*)c1i, (const float2*)c2i, out);
    scan_pass3<<<(NCHUNK * LANE2) / 256, 256>>>((const float2*)di, out);
}

// round 15
// speedup vs baseline: 1.8688x; 1.2230x over previous
#include <cuda_runtime.h>
#include <cuda_bf16.h>
#include <cuda_fp16.h>
#include <cstdint>

#define LSEQ   2048
#define BATCH  16
#define NIN    256
#define LANES  8192
#define LANE2  4096
#define ELEMS  (LSEQ * LANES)
#define NCHUNK 64
#define TCHUNK 32

#define NUSED  2560
#define KEFF   256               // single fp16 GEMM
#define NKCH   4
#define NSTAGE 3
#define STAGE_BYTES 32768
#define EPI_STRIDE 132
#define GEMM_SMEM  (NSTAGE * STAGE_BYTES)

// -------- scratch --------
__device__ __half g_u[5][ELEMS];                // fp16 planes (160MB)
__device__ __half g_xh[32768 * 256];            // A fp16
__device__ __half g_wt[NUSED * KEFF];           // B' fp16 [n-permuted][256]
__device__ float g_A1[NCHUNK * LANES];
__device__ float g_B1[NCHUNK * LANES];
__device__ float g_A2[NCHUNK * LANES];
__device__ float g_B2[NCHUNK * LANES];
__device__ float g_c1in[NCHUNK * LANES];
__device__ float g_c2in[NCHUNK * LANES];

__device__ __forceinline__ float sigmoidf_(float v) {
    return 1.0f / (1.0f + __expf(-v));
}

// ---------------- helpers ----------------
__device__ __forceinline__ uint32_t smem_u32(const void* p) {
    uint32_t a;
    asm("{ .reg .u64 t; cvta.to.shared.u64 t, %1; cvt.u32.u64 %0, t; }" : "=r"(a) : "l"(p));
    return a;
}
__device__ __forceinline__ uint32_t swz(uint32_t b) { return b ^ ((b >> 3) & 0x70); }

__device__ __forceinline__ void cp16(uint32_t dst, const void* src) {
    asm volatile("cp.async.cg.shared.global [%0], [%1], 16;" :: "r"(dst), "l"(src) : "memory");
}
__device__ __forceinline__ void ldsm4(uint32_t* r, uint32_t addr) {
    asm volatile("ldmatrix.sync.aligned.m8n8.x4.shared.b16 {%0,%1,%2,%3}, [%4];"
                 : "=r"(r[0]), "=r"(r[1]), "=r"(r[2]), "=r"(r[3]) : "r"(addr));
}
__device__ __forceinline__ void mma16816h(float* c, const uint32_t* a, const uint32_t* b) {
    asm volatile("mma.sync.aligned.m16n8k16.row.col.f32.f16.f16.f32 "
                 "{%0,%1,%2,%3}, {%4,%5,%6,%7}, {%8,%9}, {%0,%1,%2,%3};"
                 : "+f"(c[0]), "+f"(c[1]), "+f"(c[2]), "+f"(c[3])
                 : "r"(a[0]), "r"(a[1]), "r"(a[2]), "r"(a[3]), "r"(b[0]), "r"(b[1]));
}

// ---------------- prep kernels (R8) ----------------
__global__ __launch_bounds__(256)
void cvt_x(const float4* __restrict__ x)
{
    const int idx = blockIdx.x * 256 + threadIdx.x;
    float4 v = x[idx];
    __half2* hp = (__half2*)g_xh;
    hp[idx * 2 + 0] = __floats2half2_rn(v.x, v.y);
    hp[idx * 2 + 1] = __floats2half2_rn(v.z, v.w);
}

__global__ __launch_bounds__(256)
void prep_w(const float* __restrict__ W)   // [256, 3072]
{
    const int idx = blockIdx.x * 256 + threadIdx.x;
    const int p  = idx >> 8;
    const int ko = idx & 255;
    const int dn = p & 511;
    const int kg = p >> 9;
    const int jg = dn * 6 + kg;
    g_wt[idx] = __float2half_rn(W[(size_t)ko * 3072 + jg]);
}

// ---------------- fp16 HMMA GEMM (R8 exact) ----------------
__global__ __launch_bounds__(256)
void gemm_mma(const float* __restrict__ bias)
{
    extern __shared__ char smem[];
    const uint32_t sb = smem_u32(smem);
    const int tid  = threadIdx.x;
    const int warp = tid >> 5;
    const int lane = tid & 31;
    const int m0 = blockIdx.y * 128;
    const int p0 = blockIdx.x * 128;

    const int wm = warp & 3;
    const int wn = warp >> 2;
    const int rb = wm * 32;
    const int cb = wn * 64;

    const int aRow  = rb + (lane & 7) + ((lane >> 3) & 1) * 8;
    const int aCOff = ((lane >> 4) & 1) * 16;
    const int bRow  = cb + (lane & 7) + ((lane >> 4) & 1) * 8;
    const int bCOff = ((lane >> 3) & 1) * 16;

    float acc[2][8][4];
    #pragma unroll
    for (int i = 0; i < 2; i++)
        #pragma unroll
        for (int j = 0; j < 8; j++)
            #pragma unroll
            for (int k = 0; k < 4; k++) acc[i][j][k] = 0.0f;

    const int lr   = tid >> 3;
    const int lc16 = tid & 7;

    #define LOAD_STAGE(i, s)                                                            \
    do {                                                                                \
        const int kc_ = (i) << 6;                                                       \
        const uint32_t base_ = sb + (uint32_t)(s) * STAGE_BYTES;                        \
        _Pragma("unroll")                                                               \
        for (int j = 0; j < 4; j++) {                                                   \
            const int row_ = lr + j * 32;                                               \
            cp16(base_ + swz((uint32_t)(row_ * 128 + lc16 * 16)),                       \
                 g_xh + (((size_t)(m0 + row_)) << 8) + kc_ + lc16 * 8);                 \
        }                                                                               \
        _Pragma("unroll")                                                               \
        for (int j = 0; j < 4; j++) {                                                   \
            const int row_ = lr + j * 32;                                               \
            cp16(base_ + 16384u + swz((uint32_t)(row_ * 128 + lc16 * 16)),              \
                 g_wt + (size_t)(p0 + row_) * KEFF + kc_ + lc16 * 8);                   \
        }                                                                               \
        asm volatile("cp.async.commit_group;" ::: "memory");                            \
    } while (0)

    LOAD_STAGE(0, 0);
    LOAD_STAGE(1, 1);

    int stage = 0;
    for (int i = 0; i < NKCH; i++) {
        asm volatile("cp.async.wait_group 1;" ::: "memory");
        __syncthreads();

        if (i + 2 < NKCH) {
            const int s2 = (stage + 2 >= NSTAGE) ? (stage + 2 - NSTAGE) : (stage + 2);
            LOAD_STAGE(i + 2, s2);
        }

        const uint32_t aBase = sb + (uint32_t)stage * STAGE_BYTES;
        const uint32_t bBase = aBase + 16384u;

        uint32_t afr[2][2][4];
        uint32_t bfr[2][4][4];
        #pragma unroll
        for (int mf = 0; mf < 2; mf++)
            ldsm4(afr[0][mf], aBase + swz((uint32_t)((aRow + mf * 16) * 128 + aCOff)));
        #pragma unroll
        for (int nf = 0; nf < 4; nf++)
            ldsm4(bfr[0][nf], bBase + swz((uint32_t)((bRow + nf * 16) * 128 + bCOff)));

        #pragma unroll
        for (int ks = 0; ks < 4; ks++) {
            const int cur = ks & 1, nxt = cur ^ 1;
            if (ks < 3) {
                const uint32_t co = (uint32_t)((ks + 1) * 32);
                #pragma unroll
                for (int mf = 0; mf < 2; mf++)
                    ldsm4(afr[nxt][mf], aBase + swz((uint32_t)((aRow + mf * 16) * 128) + co + aCOff));
                #pragma unroll
                for (int nf = 0; nf < 4; nf++)
                    ldsm4(bfr[nxt][nf], bBase + swz((uint32_t)((bRow + nf * 16) * 128) + co + bCOff));
            }
            #pragma unroll
            for (int mf = 0; mf < 2; mf++)
                #pragma unroll
                for (int n8 = 0; n8 < 8; n8++)
                    mma16816h(acc[mf][n8], afr[cur][mf], &bfr[cur][n8 >> 1][(n8 & 1) * 2]);
        }

        stage = (stage + 1 >= NSTAGE) ? 0 : stage + 1;
    }
    #undef LOAD_STAGE

    __syncthreads();

    // -------- epilogue: acc -> smem (fp32) -> fp16 g_u plane --------
    float* smf = (float*)smem;
    {
        const int r0 = rb + (lane >> 2);
        const int c0 = cb + (lane & 3) * 2;
        #pragma unroll
        for (int mf = 0; mf < 2; mf++) {
            const int r = r0 + mf * 16;
            #pragma unroll
            for (int n8 = 0; n8 < 8; n8++) {
                const int c = c0 + n8 * 8;
                *(float2*)&smf[r * EPI_STRIDE + c]       = make_float2(acc[mf][n8][0], acc[mf][n8][1]);
                *(float2*)&smf[(r + 8) * EPI_STRIDE + c] = make_float2(acc[mf][n8][2], acc[mf][n8][3]);
            }
        }
    }
    __syncthreads();

    const int kg  = p0 >> 9;
    const int dnb = p0 & 511;
    __half* plane = g_u[kg];
    const int cc = lane * 4;
    if (kg >= 3) {
        const float* bp = bias + kg * 512 + dnb;
        float4 bv = *(const float4*)(bp + cc);
        #pragma unroll
        for (int t = 0; t < 16; t++) {
            const int r = warp * 16 + t;
            float4 v = *(float4*)&smf[r * EPI_STRIDE + cc];
            __half2 p0h = __floats2half2_rn(sigmoidf_(v.x + bv.x), sigmoidf_(v.y + bv.y));
            __half2 p1h = __floats2half2_rn(sigmoidf_(v.z + bv.z), sigmoidf_(v.w + bv.w));
            uint2 u2;
            u2.x = *(unsigned*)&p0h;
            u2.y = *(unsigned*)&p1h;
            *(uint2*)(plane + (size_t)(m0 + r) * 512 + dnb + cc) = u2;
        }
    } else {
        #pragma unroll
        for (int t = 0; t < 16; t++) {
            const int r = warp * 16 + t;
            float4 v = *(float4*)&smf[r * EPI_STRIDE + cc];
            __half2 p0h = __floats2half2_rn(v.x, v.y);
            __half2 p1h = __floats2half2_rn(v.z, v.w);
            uint2 u2;
            u2.x = *(unsigned*)&p0h;
            u2.y = *(unsigned*)&p1h;
            *(uint2*)(plane + (size_t)(m0 + r) * 512 + dnb + cc) = u2;
        }
    }
}

// ---------------- scan ----------------
__device__ __forceinline__ float2 h2f(const __half* p, size_t idx2) {
    __half2 h = *(const __half2*)(p + idx2 * 2);
    return __half22float2(h);
}

__global__ __launch_bounds__(256)
void scan_pass1(const float2* __restrict__ d_init2)
{
    const int gid   = blockIdx.x * blockDim.x + threadIdx.x;
    const int l2    = gid & (LANE2 - 1);
    const int chunk = gid >> 12;
    const int dir   = (l2 >> 7) & 1;
    const int s0    = chunk * TCHUNK;

    float2 d;
    if (s0 == 0) d = d_init2[l2];
    else {
        const int sp = s0 - 1;
        const int tp = dir ? (LSEQ - 1 - sp) : sp;
        d = h2f(g_u[1], (size_t)tp * LANE2 + l2);
    }

    float2 A1 = {1.f, 1.f}, B1 = {0.f, 0.f}, A2 = {1.f, 1.f}, B2 = {0.f, 0.f};
    #pragma unroll 4
    for (int i = 0; i < TCHUNK; i++) {
        const int s = s0 + i;
        const int t = dir ? (LSEQ - 1 - s) : s;
        const size_t b = (size_t)t * LANE2 + l2;
        float2 x1 = h2f(g_u[0], b);
        float2 x2 = h2f(g_u[1], b);
        float2 x3 = h2f(g_u[2], b);
        float2 f1 = h2f(g_u[3], b);
        float2 f2 = h2f(g_u[4], b);
        A1.x *= f1.x; A1.y *= f1.y;
        B1.x = f1.x * B1.x + (1.f - f1.x) * x1.x;
        B1.y = f1.y * B1.y + (1.f - f1.y) * x1.y;
        float tx = x3.x * d.x, ty = x3.y * d.y;
        A2.x *= f2.x; A2.y *= f2.y;
        B2.x = f2.x * B2.x + (1.f - f2.x) * tx;
        B2.y = f2.y * B2.y + (1.f - f2.y) * ty;
        d = x2;
    }
    const int o = chunk * LANE2 + l2;
    ((float2*)g_A1)[o] = A1; ((float2*)g_B1)[o] = B1;
    ((float2*)g_A2)[o] = A2; ((float2*)g_B2)[o] = B2;
}

// scalar lanes (8192 threads = 32 CTAs), manual depth-1 prefetch
__global__ __launch_bounds__(256)
void scan_pass2(const float* __restrict__ c1_init,
                const float* __restrict__ c2_init,
                float* __restrict__ out)
{
    const int l = blockIdx.x * blockDim.x + threadIdx.x;   // 0..8191
    float c1 = c1_init[l];
    float c2 = c2_init[l];

    float A1 = g_A1[l], B1 = g_B1[l], A2 = g_A2[l], B2 = g_B2[l];
    for (int c = 0; c < NCHUNK; c++) {
        const int o = c * LANES + l;
        g_c1in[o] = c1;
        g_c2in[o] = c2;
        float nA1, nB1, nA2, nB2;
        if (c + 1 < NCHUNK) {
            const int n = o + LANES;
            nA1 = g_A1[n]; nB1 = g_B1[n];
            nA2 = g_A2[n]; nB2 = g_B2[n];
        }
        c1 = fmaf(A1, c1, B1);
        c2 = fmaf(A2, c2, B2);
        A1 = nA1; B1 = nB1; A2 = nA2; B2 = nB2;
    }

    const size_t tail = (size_t)2 * LSEQ * LANES;
    out[tail + l]         = c1;
    out[tail + LANES + l] = c2;
    const int dir = (l >> 8) & 1;
    const int tlast = dir ? 0 : (LSEQ - 1);
    out[tail + 2 * LANES + l] = __half2float(g_u[1][(size_t)tlast * LANES + l]);
}

__global__ __launch_bounds__(256)
void scan_pass3(const float2* __restrict__ d_init2,
                float* __restrict__ out)
{
    const int gid   = blockIdx.x * blockDim.x + threadIdx.x;
    const int l2    = gid & (LANE2 - 1);
    const int chunk = gid >> 12;
    const int dir   = (l2 >> 7) & 1;
    const int s0    = chunk * TCHUNK;

    float2 d;
    if (s0 == 0) d = d_init2[l2];
    else {
        const int sp = s0 - 1;
        const int tp = dir ? (LSEQ - 1 - sp) : sp;
        d = h2f(g_u[1], (size_t)tp * LANE2 + l2);
    }

    const int o = chunk * LANE2 + l2;
    float2 c1 = ((const float2*)g_c1in)[o];
    float2 c2 = ((const float2*)g_c2in)[o];
    float2* out_c1 = (float2*)out;
    float2* out_c2 = out_c1 + (size_t)LSEQ * LANE2;

    #pragma unroll 4
    for (int i = 0; i < TCHUNK; i++) {
        const int s = s0 + i;
        const int t = dir ? (LSEQ - 1 - s) : s;
        const size_t b = (size_t)t * LANE2 + l2;
        float2 x1 = h2f(g_u[0], b);
        float2 x2 = h2f(g_u[1], b);
        float2 x3 = h2f(g_u[2], b);
        float2 f1 = h2f(g_u[3], b);
        float2 f2 = h2f(g_u[4], b);
        c1.x = (c1.x - x1.x) * f1.x + x1.x;
        c1.y = (c1.y - x1.y) * f1.y + x1.y;
        float tx = x3.x * d.x, ty = x3.y * d.y;
        c2.x = (c2.x - tx) * f2.x + tx;
        c2.y = (c2.y - ty) * f2.y + ty;
        d = x2;
        out_c1[b] = c1;
        out_c2[b] = c2;
    }
}

// ======================================================================
extern "C" void kernel_launch(void* const* d_in, const int* in_sizes, int n_in,
                              void* d_out, int out_size)
{
    const float* x    = (const float*)d_in[0];
    const float* w    = (const float*)d_in[1];
    const float* bias = (const float*)d_in[2];
    const float* c1i  = (const float*)d_in[3];
    const float* c2i  = (const float*)d_in[4];
    const float* di   = (const float*)d_in[5];
    float* out = (float*)d_out;

    static int attr_set = 0;
    if (!attr_set) {
        cudaFuncSetAttribute(gemm_mma, cudaFuncAttributeMaxDynamicSharedMemorySize, GEMM_SMEM);
        attr_set = 1;
    }

    cvt_x<<<8192, 256>>>((const float4*)x);
    prep_w<<<2560, 256>>>(w);
    gemm_mma<<<dim3(20, 256), 256, GEMM_SMEM>>>(bias);

    scan_pass1<<<(NCHUNK * LANE2) / 256, 256>>>((const float2*)di);
    scan_pass2<<<LANES / 256, 256>>>(c1i, c2i, out);
    scan_pass3<<<(NCHUNK * LANE2) / 256, 256>>>((const float2*)di, out);
}